// round 1
// baseline (speedup 1.0000x reference)
#include <cuda_runtime.h>
#include <cuda_bf16.h>
#include <cstdint>

// Problem constants
#define Hdim 64
#define Wdim 64
#define Bn   8
#define HIDc 32
#define Tn   16
#define CINx 16

// Tiling
#define CC   8          // input-channel chunk staged in smem
#define TH   8          // y-rows per block
#define SSTR 66         // smem input row stride (64 + 2 halo)

// Persistent cell state (device globals; NOT allocated, per harness rules).
__device__ float g_c0[(size_t)Bn * HIDc * Hdim * Wdim];
__device__ float g_c1[(size_t)Bn * HIDc * Hdim * Wdim];

__device__ __forceinline__ float sigm(float v) {
    return __fdividef(1.0f, 1.0f + __expf(-v));
}
__device__ __forceinline__ float tanh_fast(float v) {
    // tanh(x) = 2*sigmoid(2x) - 1
    return 2.0f * sigm(2.0f * v) - 1.0f;
}

// One ConvLSTM step for one layer.
// Grid: (Hdim/TH, Bn, 8 hidden-channel groups of 4). Block: 256 threads.
// Thread (ty, txp): row ty of tile, x positions {2*txp, 2*txp+1}.
// Accumulates 4 gates x 4 hidden channels x 2 x-positions = 32 fp32 accumulators.
template<int CIN_X, int LAYER>
__global__ __launch_bounds__(256)
void step_kernel(const float* __restrict__ xsrc,   // [B, CIN_X, H, W]
                 const float* __restrict__ hsrc,   // [B, 32, H, W] or null at t==0
                 const float* __restrict__ Wt,     // [128, CIN_X+32, 3, 3]
                 const float* __restrict__ bias,   // [128]
                 float* __restrict__ h_out,        // [B, 32, H, W] (this t's h_seq slab)
                 int t0)
{
    constexpr int CIN_TOT = CIN_X + HIDc;
    __shared__ float s_in[CC * 10 * SSTR];
    __shared__ __align__(16) float s_w[CC * 9 * 16];

    float* c_state = (LAYER == 0) ? g_c0 : g_c1;

    const int tid = threadIdx.x;
    const int txp = tid & 31;
    const int ty  = tid >> 5;
    const int x0  = txp * 2;
    const int gy0 = blockIdx.x * TH;
    const int b   = blockIdx.y;
    const int hcg = blockIdx.z;

    float acc0[16], acc1[16];
#pragma unroll
    for (int g = 0; g < 16; g++) { acc0[g] = 0.0f; acc1[g] = 0.0f; }

    for (int cc0 = 0; cc0 < CIN_TOT; cc0 += CC) {
        // ---- stage input patch (CC channels, 10 rows, 66 cols, zero-padded) ----
        for (int idx = tid; idx < CC * 10 * SSTR; idx += 256) {
            int ci  = idx / (10 * SSTR);
            int rem = idx - ci * (10 * SSTR);
            int r   = rem / SSTR;
            int col = rem - r * SSTR;
            int y = gy0 - 1 + r;
            int x = col - 1;
            float v = 0.0f;
            int c = cc0 + ci;
            if (y >= 0 && y < Hdim && x >= 0 && x < Wdim) {
                if (c < CIN_X)
                    v = xsrc[((size_t)(b * CIN_X + c) * Hdim + y) * Wdim + x];
                else if (!t0)
                    v = hsrc[((size_t)(b * HIDc + (c - CIN_X)) * Hdim + y) * Wdim + x];
            }
            s_in[idx] = v;
        }
        // ---- stage weights: layout [ci][ky*3+kx][16 gate-channels] ----
        for (int idx = tid; idx < CC * 9 * 16; idx += 256) {
            int ci  = idx / 144;
            int rem = idx - ci * 144;
            int k   = rem >> 4;       // ky*3+kx
            int gi  = rem & 15;       // gate*4 + hci
            int oc  = (gi >> 2) * HIDc + hcg * 4 + (gi & 3);
            s_w[idx] = Wt[((size_t)oc * CIN_TOT + (cc0 + ci)) * 9 + k];
        }
        __syncthreads();

        // ---- compute ----
#pragma unroll
        for (int ci = 0; ci < CC; ci++) {
#pragma unroll
            for (int ky = 0; ky < 3; ky++) {
                const float* row = &s_in[(ci * 10 + ty + ky) * SSTR + x0];
                float v0 = row[0], v1 = row[1], v2 = row[2], v3 = row[3];
#pragma unroll
                for (int kx = 0; kx < 3; kx++) {
                    float a  = (kx == 0) ? v0 : ((kx == 1) ? v1 : v2);
                    float bb = (kx == 0) ? v1 : ((kx == 1) ? v2 : v3);
                    const float4* w4 =
                        (const float4*)&s_w[((ci * 3 + ky) * 3 + kx) * 16];
#pragma unroll
                    for (int q = 0; q < 4; q++) {
                        float4 w = w4[q];
                        acc0[4 * q + 0] += a * w.x;
                        acc0[4 * q + 1] += a * w.y;
                        acc0[4 * q + 2] += a * w.z;
                        acc0[4 * q + 3] += a * w.w;
                        acc1[4 * q + 0] += bb * w.x;
                        acc1[4 * q + 1] += bb * w.y;
                        acc1[4 * q + 2] += bb * w.z;
                        acc1[4 * q + 3] += bb * w.w;
                    }
                }
            }
        }
        __syncthreads();
    }

    // ---- gate math + state update ----
    const int y = gy0 + ty;
#pragma unroll
    for (int hci = 0; hci < 4; hci++) {
        int hc = hcg * 4 + hci;
        float bi = bias[hc];
        float bf = bias[HIDc + hc];
        float bo = bias[2 * HIDc + hc];
        float bg = bias[3 * HIDc + hc];
        size_t off = ((size_t)(b * HIDc + hc) * Hdim + y) * Wdim + x0;

        float2 cp = make_float2(0.0f, 0.0f);
        if (!t0) cp = *(const float2*)(c_state + off);

        float i0 = acc0[hci]       + bi;
        float f0 = acc0[4 + hci]   + bf;
        float o0 = acc0[8 + hci]   + bo;
        float g0 = acc0[12 + hci]  + bg;
        float i1 = acc1[hci]       + bi;
        float f1 = acc1[4 + hci]   + bf;
        float o1 = acc1[8 + hci]   + bo;
        float g1 = acc1[12 + hci]  + bg;

        float cn0 = sigm(f0) * cp.x + sigm(i0) * tanh_fast(g0);
        float cn1 = sigm(f1) * cp.y + sigm(i1) * tanh_fast(g1);
        float hn0 = sigm(o0) * tanh_fast(cn0);
        float hn1 = sigm(o1) * tanh_fast(cn1);

        *(float2*)(c_state + off) = make_float2(cn0, cn1);
        *(float2*)(h_out + off)   = make_float2(hn0, hn1);
    }
}

// Writes the four tail regions: h0_T, c0_T, h1_T, c1_T.
__global__ void tail_copy(float* __restrict__ out)
{
    const size_t NP = (size_t)Bn * HIDc * Hdim * Wdim;     // 1048576
    size_t i = (size_t)blockIdx.x * blockDim.x + threadIdx.x;
    if (i < NP) {
        const size_t SEQ = Tn * NP;                        // 16777216
        out[2 * SEQ + 0 * NP + i] = out[(Tn - 1) * NP + i];        // h0_T
        out[2 * SEQ + 1 * NP + i] = g_c0[i];                        // c0_T
        out[2 * SEQ + 2 * NP + i] = out[SEQ + (Tn - 1) * NP + i];   // h1_T
        out[2 * SEQ + 3 * NP + i] = g_c1[i];                        // c1_T
    }
}

extern "C" void kernel_launch(void* const* d_in, const int* in_sizes, int n_in,
                              void* d_out, int out_size)
{
    const float* x  = (const float*)d_in[0];  // [T,B,16,64,64]
    const float* W0 = (const float*)d_in[1];  // [128,48,3,3]
    const float* b0 = (const float*)d_in[2];  // [128]
    const float* W1 = (const float*)d_in[3];  // [128,64,3,3]
    const float* b1 = (const float*)d_in[4];  // [128]
    float* out = (float*)d_out;

    const size_t XS = (size_t)Bn * CINx * Hdim * Wdim;   // 524288 per t
    const size_t HS = (size_t)Bn * HIDc * Hdim * Wdim;   // 1048576 per t
    float* hseq0 = out;
    float* hseq1 = out + (size_t)Tn * HS;

    dim3 grid(Hdim / TH, Bn, 8);

    for (int t = 0; t < Tn; t++) {
        const float* h0prev = t ? (hseq0 + (size_t)(t - 1) * HS) : nullptr;
        step_kernel<CINx, 0><<<grid, 256>>>(x + (size_t)t * XS, h0prev,
                                            W0, b0, hseq0 + (size_t)t * HS, t == 0);
        const float* h1prev = t ? (hseq1 + (size_t)(t - 1) * HS) : nullptr;
        step_kernel<HIDc, 1><<<grid, 256>>>(hseq0 + (size_t)t * HS, h1prev,
                                            W1, b1, hseq1 + (size_t)t * HS, t == 0);
    }
    tail_copy<<<(unsigned)((HS + 255) / 256), 256>>>(out);
}

// round 2
// speedup vs baseline: 1.3285x; 1.3285x over previous
#include <cuda_runtime.h>
#include <cuda_bf16.h>
#include <cstdint>

#define Hdim 64
#define Wdim 64
#define Bn   8
#define HIDc 32
#define Tn   16
#define CINx 16

#define CC   8          // input-channel chunk staged in smem (= warps/block)
#define TH   8          // y-rows per block
#define SSTR 66         // smem input row stride (64 + 2 halo)

using ull = unsigned long long;

// Persistent cell state (device globals; NOT allocated, per harness rules).
__device__ float g_c0[(size_t)Bn * HIDc * Hdim * Wdim];
__device__ float g_c1[(size_t)Bn * HIDc * Hdim * Wdim];

__device__ __forceinline__ float sigm(float v) {
    return __fdividef(1.0f, 1.0f + __expf(-v));
}
__device__ __forceinline__ float tanh_fast(float v) {
    return 2.0f * sigm(2.0f * v) - 1.0f;
}

// Packed fp32x2 FMA (sm_100a): d = a*b + d, lane-wise on two packed fp32.
__device__ __forceinline__ void ffma2(ull& d, ull a, ull b) {
    asm("fma.rn.f32x2 %0, %1, %2, %0;" : "+l"(d) : "l"(a), "l"(b));
}
// Broadcast one fp32 into both halves of a b64.
__device__ __forceinline__ ull pack2(float v) {
    ull r;
    asm("mov.b64 %0, {%1, %1};" : "=l"(r) : "f"(v));
    return r;
}
__device__ __forceinline__ float2 unpack2(ull v) {
    float2 f;
    asm("mov.b64 {%0, %1}, %2;" : "=f"(f.x), "=f"(f.y) : "l"(v));
    return f;
}

// One ConvLSTM step for one layer.
// Grid: (Hdim/TH, Bn, 8 hidden-channel groups of 4). Block: 256 threads (8 warps).
// Thread (ty=warp, lane): row ty, x-positions {2*lane, 2*lane+1}.
// Accumulators: 16 f32x2 per x-position? No — 8 channel-pairs x 2 x-positions
// = 16 b64 accumulators (32 fp32), one FFMA2 covers 2 gate-channels.
template<int CIN_X, int LAYER>
__global__ __launch_bounds__(256)
void step_kernel(const float* __restrict__ xsrc,   // [B, CIN_X, H, W]
                 const float* __restrict__ hsrc,   // [B, 32, H, W] (prev h) or null
                 const float* __restrict__ Wt,     // [128, CIN_X+32, 3, 3]
                 const float* __restrict__ bias,   // [128]
                 float* __restrict__ h_out,        // [B, 32, H, W]
                 int t0)
{
    constexpr int CIN_TOT = CIN_X + HIDc;
    __shared__ float s_in[CC * 10 * SSTR];
    __shared__ __align__(16) float s_w[CC * 9 * 16];

    float* c_state = (LAYER == 0) ? g_c0 : g_c1;

    const int tid = threadIdx.x;
    const int l   = tid & 31;          // lane
    const int ty  = tid >> 5;          // warp = row within tile (also staging channel)
    const int x0  = l * 2;
    const int gy0 = blockIdx.x * TH;
    const int b   = blockIdx.y;
    const int hcg = blockIdx.z;

    // acc[xp][pair]: pair p covers gate-channels gi=2p,2p+1 where gi = gate*4+hci
    ull acc0[8], acc1[8];
#pragma unroll
    for (int p = 0; p < 8; p++) { acc0[p] = 0ull; acc1[p] = 0ull; }

    for (int cc0 = 0; cc0 < CIN_TOT; cc0 += CC) {
        // ---- stage input patch: warp ty stages channel cc0+ty ----
        {
            const int c = cc0 + ty;
            const float* base = nullptr;
            if (c < CIN_X)
                base = xsrc + (size_t)(b * CIN_X + c) * (Hdim * Wdim);
            else if (!t0)
                base = hsrc + (size_t)(b * HIDc + (c - CIN_X)) * (Hdim * Wdim);
            float* drow = &s_in[ty * 10 * SSTR];
#pragma unroll
            for (int r = 0; r < 10; r++) {
                const int y = gy0 - 1 + r;
                const bool yok = (base != nullptr) & (y >= 0) & (y < Hdim);
                float v0 = 0.0f, v1 = 0.0f, v2 = 0.0f;
                if (yok) {
                    const float* srow = base + (size_t)y * Wdim;
                    if (l >= 1) v0 = srow[l - 1];      // col = l   -> x = l-1
                    v1 = srow[l + 31];                  // col = l+32 -> x = l+31 (always in)
                    if (l == 0) v2 = srow[63];          // col = 64 -> x = 63
                }
                drow[l] = v0;
                drow[l + 32] = v1;
                if (l < 2) drow[l + 64] = v2;           // col 65 -> pad 0
                drow += SSTR;
            }
        }
        // ---- stage weights: [ci][ky*3+kx][16 gate-channels] ----
#pragma unroll
        for (int it = 0; it < 5; it++) {
            int idx = tid + it * 256;
            if (idx < CC * 9 * 16) {
                int ci  = idx / 144;
                int rem = idx - ci * 144;
                int k   = rem >> 4;
                int gi  = rem & 15;
                int oc  = (gi >> 2) * HIDc + hcg * 4 + (gi & 3);
                s_w[idx] = Wt[((size_t)oc * CIN_TOT + (cc0 + ci)) * 9 + k];
            }
        }
        __syncthreads();

        // ---- compute ----
#pragma unroll 4
        for (int ci = 0; ci < CC; ci++) {
#pragma unroll
            for (int ky = 0; ky < 3; ky++) {
                const float2* rp =
                    (const float2*)&s_in[(ci * 10 + ty + ky) * SSTR + x0];
                float2 v01 = rp[0];
                float2 v23 = rp[1];
                ull p0 = pack2(v01.x), p1 = pack2(v01.y);
                ull p2 = pack2(v23.x), p3 = pack2(v23.y);
                const ulonglong2* wp =
                    (const ulonglong2*)&s_w[(ci * 3 + ky) * 3 * 16];
#pragma unroll
                for (int kx = 0; kx < 3; kx++) {
                    ull a2 = (kx == 0) ? p0 : ((kx == 1) ? p1 : p2);
                    ull b2 = (kx == 0) ? p1 : ((kx == 1) ? p2 : p3);
                    ulonglong2 w0 = wp[kx * 4 + 0];
                    ulonglong2 w1 = wp[kx * 4 + 1];
                    ulonglong2 w2 = wp[kx * 4 + 2];
                    ulonglong2 w3 = wp[kx * 4 + 3];
                    ffma2(acc0[0], a2, w0.x); ffma2(acc1[0], b2, w0.x);
                    ffma2(acc0[1], a2, w0.y); ffma2(acc1[1], b2, w0.y);
                    ffma2(acc0[2], a2, w1.x); ffma2(acc1[2], b2, w1.x);
                    ffma2(acc0[3], a2, w1.y); ffma2(acc1[3], b2, w1.y);
                    ffma2(acc0[4], a2, w2.x); ffma2(acc1[4], b2, w2.x);
                    ffma2(acc0[5], a2, w2.y); ffma2(acc1[5], b2, w2.y);
                    ffma2(acc0[6], a2, w3.x); ffma2(acc1[6], b2, w3.x);
                    ffma2(acc0[7], a2, w3.y); ffma2(acc1[7], b2, w3.y);
                }
            }
        }
        __syncthreads();
    }

    // ---- gate math + state update ----
    const int y = gy0 + ty;
#pragma unroll
    for (int hci = 0; hci < 4; hci++) {
        const int hc = hcg * 4 + hci;
        const float bi = __ldg(&bias[hc]);
        const float bf = __ldg(&bias[HIDc + hc]);
        const float bo = __ldg(&bias[2 * HIDc + hc]);
        const float bg = __ldg(&bias[3 * HIDc + hc]);
        const size_t off = ((size_t)(b * HIDc + hc) * Hdim + y) * Wdim + x0;

        // pair index for (gate g, hci): p = g*2 + (hci>>1); lane = hci&1
        const int ph = hci >> 1;
        float2 I0 = unpack2(acc0[0 + ph]), I1 = unpack2(acc1[0 + ph]);
        float2 F0 = unpack2(acc0[2 + ph]), F1 = unpack2(acc1[2 + ph]);
        float2 O0 = unpack2(acc0[4 + ph]), O1 = unpack2(acc1[4 + ph]);
        float2 G0 = unpack2(acc0[6 + ph]), G1 = unpack2(acc1[6 + ph]);
        const bool hi = (hci & 1);
        float i0 = (hi ? I0.y : I0.x) + bi, i1 = (hi ? I1.y : I1.x) + bi;
        float f0 = (hi ? F0.y : F0.x) + bf, f1 = (hi ? F1.y : F1.x) + bf;
        float o0 = (hi ? O0.y : O0.x) + bo, o1 = (hi ? O1.y : O1.x) + bo;
        float g0 = (hi ? G0.y : G0.x) + bg, g1 = (hi ? G1.y : G1.x) + bg;

        float2 cp = make_float2(0.0f, 0.0f);
        if (!t0) cp = *(const float2*)(c_state + off);

        float cn0 = sigm(f0) * cp.x + sigm(i0) * tanh_fast(g0);
        float cn1 = sigm(f1) * cp.y + sigm(i1) * tanh_fast(g1);
        float hn0 = sigm(o0) * tanh_fast(cn0);
        float hn1 = sigm(o1) * tanh_fast(cn1);

        *(float2*)(c_state + off) = make_float2(cn0, cn1);
        *(float2*)(h_out + off)   = make_float2(hn0, hn1);
    }
}

// Writes the four tail regions: h0_T, c0_T, h1_T, c1_T.
__global__ void tail_copy(float* __restrict__ out)
{
    const size_t NP = (size_t)Bn * HIDc * Hdim * Wdim;     // 1048576
    size_t i = (size_t)blockIdx.x * blockDim.x + threadIdx.x;
    if (i < NP) {
        const size_t SEQ = Tn * NP;
        out[2 * SEQ + 0 * NP + i] = out[(Tn - 1) * NP + i];          // h0_T
        out[2 * SEQ + 1 * NP + i] = g_c0[i];                          // c0_T
        out[2 * SEQ + 2 * NP + i] = out[SEQ + (Tn - 1) * NP + i];     // h1_T
        out[2 * SEQ + 3 * NP + i] = g_c1[i];                          // c1_T
    }
}

extern "C" void kernel_launch(void* const* d_in, const int* in_sizes, int n_in,
                              void* d_out, int out_size)
{
    const float* x  = (const float*)d_in[0];  // [T,B,16,64,64]
    const float* W0 = (const float*)d_in[1];  // [128,48,3,3]
    const float* b0 = (const float*)d_in[2];  // [128]
    const float* W1 = (const float*)d_in[3];  // [128,64,3,3]
    const float* b1 = (const float*)d_in[4];  // [128]
    float* out = (float*)d_out;

    const size_t XS = (size_t)Bn * CINx * Hdim * Wdim;
    const size_t HS = (size_t)Bn * HIDc * Hdim * Wdim;
    float* hseq0 = out;
    float* hseq1 = out + (size_t)Tn * HS;

    dim3 grid(Hdim / TH, Bn, 8);

    for (int t = 0; t < Tn; t++) {
        const float* h0prev = t ? (hseq0 + (size_t)(t - 1) * HS) : nullptr;
        step_kernel<CINx, 0><<<grid, 256>>>(x + (size_t)t * XS, h0prev,
                                            W0, b0, hseq0 + (size_t)t * HS, t == 0);
        const float* h1prev = t ? (hseq1 + (size_t)(t - 1) * HS) : nullptr;
        step_kernel<HIDc, 1><<<grid, 256>>>(hseq0 + (size_t)t * HS, h1prev,
                                            W1, b1, hseq1 + (size_t)t * HS, t == 0);
    }
    tail_copy<<<(unsigned)((HS + 255) / 256), 256>>>(out);
}

// round 4
// speedup vs baseline: 1.4934x; 1.1242x over previous
#include <cuda_runtime.h>
#include <cuda_bf16.h>
#include <cstdint>

#define Hdim 64
#define Wdim 64
#define Bn   8
#define HIDc 32
#define Tn   16
#define CINx 16

#define CC   16         // input-channel chunk staged in smem (2 per warp)
#define TH   8          // y-rows per block
#define SSTR 66         // smem input row stride (64 + 2 halo)

#define S_IN_ELEMS  (CC * 10 * SSTR)       // 10560 floats = 42240 B
#define S_W_ELEMS   (CC * 9 * 16)          //  2304 floats =  9216 B
#define SMEM_BYTES  ((S_IN_ELEMS + S_W_ELEMS) * 4)   // 51456 B

using ull = unsigned long long;

// Persistent cell state (device globals; NOT allocated, per harness rules).
__device__ float g_c0[(size_t)Bn * HIDc * Hdim * Wdim];
__device__ float g_c1[(size_t)Bn * HIDc * Hdim * Wdim];

__device__ __forceinline__ float sigm(float v) {
    return __fdividef(1.0f, 1.0f + __expf(-v));
}
__device__ __forceinline__ float tanh_fast(float v) {
    return 2.0f * sigm(2.0f * v) - 1.0f;
}

// Packed fp32x2 FMA (sm_100a): d = a*b + d, lane-wise on two packed fp32.
__device__ __forceinline__ void ffma2(ull& d, ull a, ull b) {
    asm("fma.rn.f32x2 %0, %1, %2, %0;" : "+l"(d) : "l"(a), "l"(b));
}
__device__ __forceinline__ ull pack2(float v) {
    ull r;
    asm("mov.b64 %0, {%1, %1};" : "=l"(r) : "f"(v));
    return r;
}
__device__ __forceinline__ float2 unpack2(ull v) {
    float2 f;
    asm("mov.b64 {%0, %1}, %2;" : "=f"(f.x), "=f"(f.y) : "l"(v));
    return f;
}

// One ConvLSTM step for one layer.
// Grid: (Hdim/TH, Bn, 8 hidden-channel groups of 4). Block: 256 threads (8 warps).
// Thread (ty=warp, lane): row ty, x-positions {2*lane, 2*lane+1}.
// 16 b64 accumulators = 2 x-positions x 16 gate-channels.
template<int CIN_X, int LAYER>
__global__ __launch_bounds__(256, 4)
void step_kernel(const float* __restrict__ xsrc,   // [B, CIN_X, H, W]
                 const float* __restrict__ hsrc,   // [B, 32, H, W] (prev h) or null
                 const float* __restrict__ Wt,     // [128, CIN_X+32, 3, 3]
                 const float* __restrict__ bias,   // [128]
                 float* __restrict__ h_out,        // [B, 32, H, W]
                 int t0)
{
    constexpr int CIN_TOT = CIN_X + HIDc;            // 48 or 64
    extern __shared__ __align__(16) float smem[];
    float* s_in = smem;                              // CC*10*SSTR
    float* s_w  = smem + S_IN_ELEMS;                 // CC*9*16 (16B aligned: 10560*4=42240, /16 ok)

    float* c_state = (LAYER == 0) ? g_c0 : g_c1;

    const int tid = threadIdx.x;
    const int l   = tid & 31;
    const int ty  = tid >> 5;
    const int x0  = l * 2;
    const int gy0 = blockIdx.x * TH;
    const int b   = blockIdx.y;
    const int hcg = blockIdx.z;

    ull acc0[8], acc1[8];
#pragma unroll
    for (int p = 0; p < 8; p++) { acc0[p] = 0ull; acc1[p] = 0ull; }

    for (int cc0 = 0; cc0 < CIN_TOT; cc0 += CC) {
        // ---- stage input patch: warp ty stages channels cc0+2*ty, cc0+2*ty+1 ----
#pragma unroll
        for (int sub = 0; sub < 2; sub++) {
            const int cl = 2 * ty + sub;             // local channel 0..15
            const int c  = cc0 + cl;
            const float* base = nullptr;
            if (c < CIN_X)
                base = xsrc + (size_t)(b * CIN_X + c) * (Hdim * Wdim);
            else if (!t0)
                base = hsrc + (size_t)(b * HIDc + (c - CIN_X)) * (Hdim * Wdim);
            float* drow = &s_in[cl * 10 * SSTR];
#pragma unroll
            for (int r = 0; r < 10; r++) {
                const int y = gy0 - 1 + r;
                const bool yok = (base != nullptr) & (y >= 0) & (y < Hdim);
                float v0 = 0.0f, v1 = 0.0f, v2 = 0.0f;
                if (yok) {
                    const float* srow = base + (size_t)y * Wdim;
                    if (l >= 1) v0 = srow[l - 1];
                    v1 = srow[l + 31];
                    if (l == 0) v2 = srow[63];
                }
                drow[l] = v0;
                drow[l + 32] = v1;
                if (l < 2) drow[l + 64] = v2;
                drow += SSTR;
            }
        }
        // ---- stage weights: [ci][ky*3+kx][16 gate-channels]; 2304 = 9*256 ----
#pragma unroll
        for (int it = 0; it < 9; it++) {
            const int idx = tid + it * 256;
            const int ci  = idx / 144;
            const int rem = idx - ci * 144;
            const int k   = rem >> 4;
            const int gi  = rem & 15;
            const int oc  = (gi >> 2) * HIDc + hcg * 4 + (gi & 3);
            s_w[idx] = Wt[((size_t)oc * CIN_TOT + (cc0 + ci)) * 9 + k];
        }
        __syncthreads();

        // ---- compute ----
#pragma unroll 4
        for (int ci = 0; ci < CC; ci++) {
#pragma unroll
            for (int ky = 0; ky < 3; ky++) {
                const float2* rp =
                    (const float2*)&s_in[(ci * 10 + ty + ky) * SSTR + x0];
                float2 v01 = rp[0];
                float2 v23 = rp[1];
                ull p0 = pack2(v01.x), p1 = pack2(v01.y);
                ull p2 = pack2(v23.x), p3 = pack2(v23.y);
                const ulonglong2* wp =
                    (const ulonglong2*)&s_w[(ci * 3 + ky) * 3 * 16];
#pragma unroll
                for (int kx = 0; kx < 3; kx++) {
                    ull a2 = (kx == 0) ? p0 : ((kx == 1) ? p1 : p2);
                    ull b2 = (kx == 0) ? p1 : ((kx == 1) ? p2 : p3);
                    ulonglong2 w0 = wp[kx * 4 + 0];
                    ulonglong2 w1 = wp[kx * 4 + 1];
                    ulonglong2 w2 = wp[kx * 4 + 2];
                    ulonglong2 w3 = wp[kx * 4 + 3];
                    ffma2(acc0[0], a2, w0.x); ffma2(acc1[0], b2, w0.x);
                    ffma2(acc0[1], a2, w0.y); ffma2(acc1[1], b2, w0.y);
                    ffma2(acc0[2], a2, w1.x); ffma2(acc1[2], b2, w1.x);
                    ffma2(acc0[3], a2, w1.y); ffma2(acc1[3], b2, w1.y);
                    ffma2(acc0[4], a2, w2.x); ffma2(acc1[4], b2, w2.x);
                    ffma2(acc0[5], a2, w2.y); ffma2(acc1[5], b2, w2.y);
                    ffma2(acc0[6], a2, w3.x); ffma2(acc1[6], b2, w3.x);
                    ffma2(acc0[7], a2, w3.y); ffma2(acc1[7], b2, w3.y);
                }
            }
        }
        __syncthreads();
    }

    // ---- gate math + state update ----
    const int y = gy0 + ty;
#pragma unroll
    for (int hci = 0; hci < 4; hci++) {
        const int hc = hcg * 4 + hci;
        const float bi = __ldg(&bias[hc]);
        const float bf = __ldg(&bias[HIDc + hc]);
        const float bo = __ldg(&bias[2 * HIDc + hc]);
        const float bg = __ldg(&bias[3 * HIDc + hc]);
        const size_t off = ((size_t)(b * HIDc + hc) * Hdim + y) * Wdim + x0;

        const int ph = hci >> 1;
        float2 I0 = unpack2(acc0[0 + ph]), I1 = unpack2(acc1[0 + ph]);
        float2 F0 = unpack2(acc0[2 + ph]), F1 = unpack2(acc1[2 + ph]);
        float2 O0 = unpack2(acc0[4 + ph]), O1 = unpack2(acc1[4 + ph]);
        float2 G0 = unpack2(acc0[6 + ph]), G1 = unpack2(acc1[6 + ph]);
        const bool hi = (hci & 1);
        float i0 = (hi ? I0.y : I0.x) + bi, i1 = (hi ? I1.y : I1.x) + bi;
        float f0 = (hi ? F0.y : F0.x) + bf, f1 = (hi ? F1.y : F1.x) + bf;
        float o0 = (hi ? O0.y : O0.x) + bo, o1 = (hi ? O1.y : O1.x) + bo;
        float g0 = (hi ? G0.y : G0.x) + bg, g1 = (hi ? G1.y : G1.x) + bg;

        float2 cp = make_float2(0.0f, 0.0f);
        if (!t0) cp = *(const float2*)(c_state + off);

        float cn0 = sigm(f0) * cp.x + sigm(i0) * tanh_fast(g0);
        float cn1 = sigm(f1) * cp.y + sigm(i1) * tanh_fast(g1);
        float hn0 = sigm(o0) * tanh_fast(cn0);
        float hn1 = sigm(o1) * tanh_fast(cn1);

        *(float2*)(c_state + off) = make_float2(cn0, cn1);
        *(float2*)(h_out + off)   = make_float2(hn0, hn1);
    }
}

// Writes the four tail regions: h0_T, c0_T, h1_T, c1_T.
__global__ void tail_copy(float* __restrict__ out)
{
    const size_t NP = (size_t)Bn * HIDc * Hdim * Wdim;     // 1048576 floats
    size_t i4 = (size_t)blockIdx.x * blockDim.x + threadIdx.x;
    const size_t N4 = NP / 4;
    if (i4 < N4) {
        const size_t SEQ = Tn * NP;
        float4* o4 = (float4*)out;
        const float4* c0 = (const float4*)g_c0;
        const float4* c1 = (const float4*)g_c1;
        const size_t base = (2 * SEQ) / 4;
        o4[base + 0 * N4 + i4] = o4[((Tn - 1) * NP) / 4 + i4];        // h0_T
        o4[base + 1 * N4 + i4] = c0[i4];                               // c0_T
        o4[base + 2 * N4 + i4] = o4[(SEQ + (Tn - 1) * NP) / 4 + i4];   // h1_T
        o4[base + 3 * N4 + i4] = c1[i4];                               // c1_T
    }
}

extern "C" void kernel_launch(void* const* d_in, const int* in_sizes, int n_in,
                              void* d_out, int out_size)
{
    const float* x  = (const float*)d_in[0];  // [T,B,16,64,64]
    const float* W0 = (const float*)d_in[1];  // [128,48,3,3]
    const float* b0 = (const float*)d_in[2];  // [128]
    const float* W1 = (const float*)d_in[3];  // [128,64,3,3]
    const float* b1 = (const float*)d_in[4];  // [128]
    float* out = (float*)d_out;

    // Opt in to >48KB dynamic smem (non-stream call; deterministic, idempotent).
    cudaFuncSetAttribute(step_kernel<CINx, 0>,
                         cudaFuncAttributeMaxDynamicSharedMemorySize, SMEM_BYTES);
    cudaFuncSetAttribute(step_kernel<HIDc, 1>,
                         cudaFuncAttributeMaxDynamicSharedMemorySize, SMEM_BYTES);

    const size_t XS = (size_t)Bn * CINx * Hdim * Wdim;
    const size_t HS = (size_t)Bn * HIDc * Hdim * Wdim;
    float* hseq0 = out;
    float* hseq1 = out + (size_t)Tn * HS;

    dim3 grid(Hdim / TH, Bn, 8);

    for (int t = 0; t < Tn; t++) {
        const float* h0prev = t ? (hseq0 + (size_t)(t - 1) * HS) : nullptr;
        step_kernel<CINx, 0><<<grid, 256, SMEM_BYTES>>>(
            x + (size_t)t * XS, h0prev, W0, b0, hseq0 + (size_t)t * HS, t == 0);
        const float* h1prev = t ? (hseq1 + (size_t)(t - 1) * HS) : nullptr;
        step_kernel<HIDc, 1><<<grid, 256, SMEM_BYTES>>>(
            hseq0 + (size_t)t * HS, h1prev, W1, b1, hseq1 + (size_t)t * HS, t == 0);
    }
    tail_copy<<<(unsigned)((HS / 4 + 255) / 256), 256>>>(out);
}

// round 5
// speedup vs baseline: 1.5506x; 1.0383x over previous
#include <cuda_runtime.h>
#include <cuda_bf16.h>
#include <cstdint>

#define Hdim 64
#define Wdim 64
#define Bn   8
#define HIDc 32
#define Tn   16
#define CINx 16

#define CC   8          // input-channel chunk staged in smem (1 per warp)
#define TH   16         // y-rows per block (8 warps x 2 rows)
#define SSTR 68         // smem input row stride (64 + 2 halo + pad to 4-float mult)

using ull = unsigned long long;

// Persistent cell state (device globals; NOT allocated, per harness rules).
__device__ float g_c0[(size_t)Bn * HIDc * Hdim * Wdim];
__device__ float g_c1[(size_t)Bn * HIDc * Hdim * Wdim];

__device__ __forceinline__ float sigm(float v) {
    return __fdividef(1.0f, 1.0f + __expf(-v));
}
__device__ __forceinline__ float tanh_fast(float v) {
    return 2.0f * sigm(2.0f * v) - 1.0f;
}

// Packed fp32x2 FMA (sm_100a): d = a*b + d, lane-wise on two packed fp32.
__device__ __forceinline__ void ffma2(ull& d, ull a, ull b) {
    asm("fma.rn.f32x2 %0, %1, %2, %0;" : "+l"(d) : "l"(a), "l"(b));
}
__device__ __forceinline__ ull pack2(float v) {
    ull r;
    asm("mov.b64 %0, {%1, %1};" : "=l"(r) : "f"(v));
    return r;
}
__device__ __forceinline__ float2 unpack2(ull v) {
    float2 f;
    asm("mov.b64 {%0, %1}, %2;" : "=f"(f.x), "=f"(f.y) : "l"(v));
    return f;
}

// One ConvLSTM step for one layer.
// Grid: (Hdim/TH=4, Bn, 16 hidden-channel groups of 2). Block: 256 threads.
// Warp ty covers rows {2ty, 2ty+1}; lane l: sub-row l>>4, x0 = (l&15)*4.
// Each thread: 4 x-positions x (4 gates x 2 hidden channels).
// Accumulators: acc[xp][gate] as b64 = (hc0, hc1) packed.
template<int CIN_X, int LAYER>
__global__ __launch_bounds__(256, 4)
void step_kernel(const float* __restrict__ xsrc,   // [B, CIN_X, H, W]
                 const float* __restrict__ hsrc,   // [B, 32, H, W] (prev h) or null
                 const float* __restrict__ Wt,     // [128, CIN_X+32, 3, 3]
                 const float* __restrict__ bias,   // [128]
                 float* __restrict__ h_out,        // [B, 32, H, W]
                 int t0)
{
    constexpr int CIN_TOT = CIN_X + HIDc;                 // 48 or 64
    __shared__ __align__(16) float s_in[CC * (TH + 2) * SSTR];  // 8*18*68 = 9792 f
    __shared__ __align__(16) float s_w[CC * 9 * 8];             // 576 f

    float* c_state = (LAYER == 0) ? g_c0 : g_c1;

    const int tid = threadIdx.x;
    const int l   = tid & 31;
    const int ty  = tid >> 5;
    const int sub = l >> 4;              // 0/1: which of the warp's two rows
    const int x0  = (l & 15) * 4;
    const int r   = ty * 2 + sub;        // row within tile, 0..15
    const int gy0 = blockIdx.x * TH;
    const int b   = blockIdx.y;
    const int hcg = blockIdx.z;          // 0..15, hidden channels {2*hcg, 2*hcg+1}

    ull acc[4][4];
#pragma unroll
    for (int xp = 0; xp < 4; xp++)
#pragma unroll
        for (int g = 0; g < 4; g++) acc[xp][g] = 0ull;

    for (int cc0 = 0; cc0 < CIN_TOT; cc0 += CC) {
        // ---- stage input patch: warp ty stages channel cc0+ty, 18 rows ----
        {
            const int c = cc0 + ty;
            const float* base = nullptr;
            if (c < CIN_X)
                base = xsrc + (size_t)(b * CIN_X + c) * (Hdim * Wdim);
            else if (!t0)
                base = hsrc + (size_t)(b * HIDc + (c - CIN_X)) * (Hdim * Wdim);
            float* drow = &s_in[ty * (TH + 2) * SSTR];
#pragma unroll
            for (int rr = 0; rr < TH + 2; rr++) {
                const int y = gy0 - 1 + rr;
                const bool yok = (base != nullptr) & (y >= 0) & (y < Hdim);
                float v0 = 0.0f, v1 = 0.0f, v2 = 0.0f;
                if (yok) {
                    const float* srow = base + (size_t)y * Wdim;
                    if (l >= 1) v0 = srow[l - 1];     // col l   -> x = l-1
                    v1 = srow[l + 31];                 // col l+32 -> x = l+31
                    if (l == 0) v2 = srow[63];         // col 64 -> x = 63
                }
                drow[l] = v0;
                drow[l + 32] = v1;
                if (l < 2) drow[l + 64] = v2;          // col 65 -> 0 pad
                drow += SSTR;
            }
        }
        // ---- stage weights: [ci][k=ky*3+kx][8 gch], gch = gate*2 + hci ----
#pragma unroll
        for (int it = 0; it < 3; it++) {
            const int idx = tid + it * 256;
            if (idx < CC * 9 * 8) {
                const int ci  = idx / 72;
                const int rem = idx - ci * 72;
                const int k   = rem >> 3;
                const int gi  = rem & 7;
                const int oc  = (gi >> 1) * HIDc + hcg * 2 + (gi & 1);
                s_w[idx] = Wt[((size_t)oc * CIN_TOT + (cc0 + ci)) * 9 + k];
            }
        }
        __syncthreads();

        // ---- compute ----
#pragma unroll 4
        for (int ci = 0; ci < CC; ci++) {
#pragma unroll
            for (int ky = 0; ky < 3; ky++) {
                const float* rowp = &s_in[(ci * (TH + 2) + r + ky) * SSTR + x0];
                float4 va = *(const float4*)rowp;          // cols x0..x0+3
                float2 vb = *(const float2*)(rowp + 4);    // cols x0+4..x0+5
                ull p0 = pack2(va.x), p1 = pack2(va.y), p2 = pack2(va.z);
                ull p3 = pack2(va.w), p4 = pack2(vb.x), p5 = pack2(vb.y);
                const ulonglong2* wp =
                    (const ulonglong2*)&s_w[(ci * 9 + ky * 3) * 8];
#pragma unroll
                for (int kx = 0; kx < 3; kx++) {
                    ull a0 = (kx == 0) ? p0 : ((kx == 1) ? p1 : p2);
                    ull a1 = (kx == 0) ? p1 : ((kx == 1) ? p2 : p3);
                    ull a2 = (kx == 0) ? p2 : ((kx == 1) ? p3 : p4);
                    ull a3 = (kx == 0) ? p3 : ((kx == 1) ? p4 : p5);
                    ulonglong2 wa = wp[kx * 2 + 0];   // gates i (hc0,hc1), f
                    ulonglong2 wb = wp[kx * 2 + 1];   // gates o, g
                    ffma2(acc[0][0], a0, wa.x); ffma2(acc[0][1], a0, wa.y);
                    ffma2(acc[0][2], a0, wb.x); ffma2(acc[0][3], a0, wb.y);
                    ffma2(acc[1][0], a1, wa.x); ffma2(acc[1][1], a1, wa.y);
                    ffma2(acc[1][2], a1, wb.x); ffma2(acc[1][3], a1, wb.y);
                    ffma2(acc[2][0], a2, wa.x); ffma2(acc[2][1], a2, wa.y);
                    ffma2(acc[2][2], a2, wb.x); ffma2(acc[2][3], a2, wb.y);
                    ffma2(acc[3][0], a3, wa.x); ffma2(acc[3][1], a3, wa.y);
                    ffma2(acc[3][2], a3, wb.x); ffma2(acc[3][3], a3, wb.y);
                }
            }
        }
        __syncthreads();
    }

    // ---- gate math + state update (4 contiguous pixels, 2 hidden channels) ----
    const int y = gy0 + r;
#pragma unroll
    for (int hci = 0; hci < 2; hci++) {
        const int hc = hcg * 2 + hci;
        const float bi = __ldg(&bias[hc]);
        const float bf = __ldg(&bias[HIDc + hc]);
        const float bo = __ldg(&bias[2 * HIDc + hc]);
        const float bg = __ldg(&bias[3 * HIDc + hc]);
        const size_t off = ((size_t)(b * HIDc + hc) * Hdim + y) * Wdim + x0;

        float4 cp = make_float4(0.0f, 0.0f, 0.0f, 0.0f);
        if (!t0) cp = *(const float4*)(c_state + off);
        float cpv[4] = {cp.x, cp.y, cp.z, cp.w};
        float cn[4], hn[4];
#pragma unroll
        for (int xp = 0; xp < 4; xp++) {
            float2 I = unpack2(acc[xp][0]);
            float2 F = unpack2(acc[xp][1]);
            float2 O = unpack2(acc[xp][2]);
            float2 G = unpack2(acc[xp][3]);
            float iv = (hci ? I.y : I.x) + bi;
            float fv = (hci ? F.y : F.x) + bf;
            float ov = (hci ? O.y : O.x) + bo;
            float gv = (hci ? G.y : G.x) + bg;
            cn[xp] = sigm(fv) * cpv[xp] + sigm(iv) * tanh_fast(gv);
            hn[xp] = sigm(ov) * tanh_fast(cn[xp]);
        }
        *(float4*)(c_state + off) = make_float4(cn[0], cn[1], cn[2], cn[3]);
        *(float4*)(h_out + off)   = make_float4(hn[0], hn[1], hn[2], hn[3]);
    }
}

// Writes the four tail regions: h0_T, c0_T, h1_T, c1_T.
__global__ void tail_copy(float* __restrict__ out)
{
    const size_t NP = (size_t)Bn * HIDc * Hdim * Wdim;     // 1048576 floats
    size_t i4 = (size_t)blockIdx.x * blockDim.x + threadIdx.x;
    const size_t N4 = NP / 4;
    if (i4 < N4) {
        const size_t SEQ = Tn * NP;
        float4* o4 = (float4*)out;
        const float4* c0 = (const float4*)g_c0;
        const float4* c1 = (const float4*)g_c1;
        const size_t base = (2 * SEQ) / 4;
        o4[base + 0 * N4 + i4] = o4[((Tn - 1) * NP) / 4 + i4];        // h0_T
        o4[base + 1 * N4 + i4] = c0[i4];                               // c0_T
        o4[base + 2 * N4 + i4] = o4[(SEQ + (Tn - 1) * NP) / 4 + i4];   // h1_T
        o4[base + 3 * N4 + i4] = c1[i4];                               // c1_T
    }
}

extern "C" void kernel_launch(void* const* d_in, const int* in_sizes, int n_in,
                              void* d_out, int out_size)
{
    const float* x  = (const float*)d_in[0];  // [T,B,16,64,64]
    const float* W0 = (const float*)d_in[1];  // [128,48,3,3]
    const float* b0 = (const float*)d_in[2];  // [128]
    const float* W1 = (const float*)d_in[3];  // [128,64,3,3]
    const float* b1 = (const float*)d_in[4];  // [128]
    float* out = (float*)d_out;

    const size_t XS = (size_t)Bn * CINx * Hdim * Wdim;
    const size_t HS = (size_t)Bn * HIDc * Hdim * Wdim;
    float* hseq0 = out;
    float* hseq1 = out + (size_t)Tn * HS;

    dim3 grid(Hdim / TH, Bn, 16);

    for (int t = 0; t < Tn; t++) {
        const float* h0prev = t ? (hseq0 + (size_t)(t - 1) * HS) : nullptr;
        step_kernel<CINx, 0><<<grid, 256>>>(
            x + (size_t)t * XS, h0prev, W0, b0, hseq0 + (size_t)t * HS, t == 0);
        const float* h1prev = t ? (hseq1 + (size_t)(t - 1) * HS) : nullptr;
        step_kernel<HIDc, 1><<<grid, 256>>>(
            hseq0 + (size_t)t * HS, h1prev, W1, b1, hseq1 + (size_t)t * HS, t == 0);
    }
    tail_copy<<<(unsigned)((HS / 4 + 255) / 256), 256>>>(out);
}